// round 15
// baseline (speedup 1.0000x reference)
#include <cuda_runtime.h>
#include <cuda_bf16.h>
#include <mma.h>

using namespace nvcuda;

#define N_PTS   524288            // = 1 << 19
#define TBITS   19
#define TMASK   ((1u << TBITS) - 1u)
#define BLOCK   256
#define PPB     128
#define LDF     68                // fp32 buf stride (floats)
#define LDAB    72                // bf16 act stride (elems)
#define LDDV    40                // bf16 dvec stride (elems)
// smem byte offsets
#define OFF_BUFF  0               // [128][68] fp32 = 34816
#define OFF_ACTH  34816           // [128][72] bf16 = 18432
#define OFF_ACTL  53248
#define OFF_DVH   71680           // [128][40] bf16 = 10240
#define OFF_DVL   81920
#define OFF_BREP0 92160           // [16][68] fp32 = 4352 each
#define OFF_BREP1 96512
#define OFF_BREP2 100864
#define OFF_BREPR 105216
#define SMEM_BYTES 109568

// Pre-split bf16 weights (hi/lo), B-matrix layout [K][N] row-major
__device__ __align__(16) __nv_bfloat16 g_w0h[32 * 64], g_w0l[32 * 64];
__device__ __align__(16) __nv_bfloat16 g_w1h[64 * 64], g_w1l[64 * 64];
__device__ __align__(16) __nv_bfloat16 g_w2h[64 * 64], g_w2l[64 * 64];
__device__ __align__(16) __nv_bfloat16 g_wrh[91 * 32], g_wrl[91 * 32];

__device__ __forceinline__ float2 ffma2(float2 a, float2 b, float2 c) {
    float2 d;
    asm("fma.rn.f32x2 %0, %1, %2, %3;"
        : "=l"(reinterpret_cast<unsigned long long&>(d))
        : "l"(reinterpret_cast<unsigned long long&>(a)),
          "l"(reinterpret_cast<unsigned long long&>(b)),
          "l"(reinterpret_cast<unsigned long long&>(c)));
    return d;
}

__constant__ float c_scale[16] = {
    16.f, 21.f, 27.f, 36.f, 48.f, 64.f, 84.f, 111.f,
    147.f, 194.f, 256.f, 337.f, 445.f, 588.f, 776.f, 1024.f
};

__device__ __forceinline__ void split1(float x, __nv_bfloat16& h, __nv_bfloat16& l) {
    h = __float2bfloat16_rn(x);
    l = __float2bfloat16_rn(x - __bfloat162float(h));
}

__device__ __forceinline__ void split4_store(float4 v, __nv_bfloat16* ph, __nv_bfloat16* pl) {
    __nv_bfloat16 h[4], l[4];
    split1(v.x, h[0], l[0]); split1(v.y, h[1], l[1]);
    split1(v.z, h[2], l[2]); split1(v.w, h[3], l[3]);
    *(uint2*)ph = *(uint2*)h;
    *(uint2*)pl = *(uint2*)l;
}

// ===================== Kernel 0: pre-split weights to bf16 hi/lo =====================
__global__ __launch_bounds__(256) void split_kernel(
    const float* __restrict__ w0, const float* __restrict__ w1,
    const float* __restrict__ w2, const float* __restrict__ wr)
{
    const int t = blockIdx.x * 256 + threadIdx.x;
    for (int k = t; k < 32 * 64; k += gridDim.x * 256) split1(w0[k], g_w0h[k], g_w0l[k]);
    for (int k = t; k < 64 * 64; k += gridDim.x * 256) {
        split1(w1[k], g_w1h[k], g_w1l[k]);
        split1(w2[k], g_w2h[k], g_w2l[k]);
    }
    for (int k = t; k < 91 * 32; k += gridDim.x * 256) split1(wr[k], g_wrh[k], g_wrl[k]);
}

// [128xK] @ [Kx64] layer; 8 warps = 2 n-groups (2 slices) x 4 m-groups (2 tiles).
// A-tile duplication 2x (was 4x), B-tile 4x (was 2x): net -20% fragment loads.
template <int NK, bool RELU>
__device__ __forceinline__ void bf16_layer64(
    const __nv_bfloat16* Ah, const __nv_bfloat16* Al,
    const __nv_bfloat16* __restrict__ Bh, const __nv_bfloat16* __restrict__ Bl,
    float* Csm, const float* brep, int w)
{
    const int n0 = (w & 1) * 32;          // 2 slices: n0, n0+16
    const int mb = (w >> 1) * 2;          // 2 m-tiles
    wmma::fragment<wmma::accumulator, 16, 16, 16, float> acc[2][2]; // [mi][ni]
    #pragma unroll
    for (int mi = 0; mi < 2; mi++)
        #pragma unroll
        for (int ni = 0; ni < 2; ni++)
            wmma::load_matrix_sync(acc[mi][ni], brep + n0 + 16 * ni, LDF, wmma::mem_row_major);

    #pragma unroll
    for (int k = 0; k < NK; k += 16) {
        wmma::fragment<wmma::matrix_b, 16, 16, 16, __nv_bfloat16, wmma::row_major> bh[2], bl[2];
        #pragma unroll
        for (int ni = 0; ni < 2; ni++) {
            wmma::load_matrix_sync(bh[ni], Bh + k * 64 + n0 + 16 * ni, 64);
            wmma::load_matrix_sync(bl[ni], Bl + k * 64 + n0 + 16 * ni, 64);
        }
        wmma::fragment<wmma::matrix_a, 16, 16, 16, __nv_bfloat16, wmma::row_major> ah[2], al[2];
        #pragma unroll
        for (int mi = 0; mi < 2; mi++) {
            wmma::load_matrix_sync(ah[mi], Ah + (mb + mi) * 16 * LDAB + k, LDAB);
            wmma::load_matrix_sync(al[mi], Al + (mb + mi) * 16 * LDAB + k, LDAB);
        }
        // term 1: ah*bh (4 independent accs)
        #pragma unroll
        for (int mi = 0; mi < 2; mi++)
            #pragma unroll
            for (int ni = 0; ni < 2; ni++)
                wmma::mma_sync(acc[mi][ni], ah[mi], bh[ni], acc[mi][ni]);
        // term 2: al*bh
        #pragma unroll
        for (int mi = 0; mi < 2; mi++)
            #pragma unroll
            for (int ni = 0; ni < 2; ni++)
                wmma::mma_sync(acc[mi][ni], al[mi], bh[ni], acc[mi][ni]);
        // term 3: ah*bl
        #pragma unroll
        for (int mi = 0; mi < 2; mi++)
            #pragma unroll
            for (int ni = 0; ni < 2; ni++)
                wmma::mma_sync(acc[mi][ni], ah[mi], bl[ni], acc[mi][ni]);
    }
    #pragma unroll
    for (int mi = 0; mi < 2; mi++)
        #pragma unroll
        for (int ni = 0; ni < 2; ni++) {
            if (RELU) {
                #pragma unroll
                for (int e = 0; e < acc[mi][ni].num_elements; e++)
                    acc[mi][ni].x[e] = fmaxf(acc[mi][ni].x[e], 0.f);
            }
            wmma::store_matrix_sync(Csm + (mb + mi) * 16 * LDF + n0 + 16 * ni,
                                    acc[mi][ni], LDF, wmma::mem_row_major);
        }
}

// RGB head: rgbh[128][32] = dv[128][32] @ wr[0:32] + bp[128][64] @ wr[27:91]
__device__ __forceinline__ void bf16_head(
    const __nv_bfloat16* bpH, const __nv_bfloat16* bpL,
    const __nv_bfloat16* dvH, const __nv_bfloat16* dvL,
    float* Csm, const float* brep, int w)
{
    const int n0 = (w & 1) * 16;
    const int mb = (w >> 1) * 2;
    wmma::fragment<wmma::accumulator, 16, 16, 16, float> acc[2];
    #pragma unroll
    for (int i = 0; i < 2; i++)
        wmma::load_matrix_sync(acc[i], brep + n0, LDF, wmma::mem_row_major);

    #pragma unroll
    for (int k = 0; k < 64; k += 16) {     // base part: wr rows 27..90
        wmma::fragment<wmma::matrix_b, 16, 16, 16, __nv_bfloat16, wmma::row_major> bh, bl;
        wmma::load_matrix_sync(bh, g_wrh + (27 + k) * 32 + n0, 32);
        wmma::load_matrix_sync(bl, g_wrl + (27 + k) * 32 + n0, 32);
        #pragma unroll
        for (int i = 0; i < 2; i++) {
            wmma::fragment<wmma::matrix_a, 16, 16, 16, __nv_bfloat16, wmma::row_major> ah, al;
            wmma::load_matrix_sync(ah, bpH + (mb + i) * 16 * LDAB + k, LDAB);
            wmma::load_matrix_sync(al, bpL + (mb + i) * 16 * LDAB + k, LDAB);
            wmma::mma_sync(acc[i], ah, bh, acc[i]);
            wmma::mma_sync(acc[i], al, bh, acc[i]);
            wmma::mma_sync(acc[i], ah, bl, acc[i]);
        }
    }
    #pragma unroll
    for (int k = 0; k < 32; k += 16) {     // dir part: wr rows 0..31 (dv cols 27..31 = 0)
        wmma::fragment<wmma::matrix_b, 16, 16, 16, __nv_bfloat16, wmma::row_major> bh, bl;
        wmma::load_matrix_sync(bh, g_wrh + k * 32 + n0, 32);
        wmma::load_matrix_sync(bl, g_wrl + k * 32 + n0, 32);
        #pragma unroll
        for (int i = 0; i < 2; i++) {
            wmma::fragment<wmma::matrix_a, 16, 16, 16, __nv_bfloat16, wmma::row_major> ah, al;
            wmma::load_matrix_sync(ah, dvH + (mb + i) * 16 * LDDV + k, LDDV);
            wmma::load_matrix_sync(al, dvL + (mb + i) * 16 * LDDV + k, LDDV);
            wmma::mma_sync(acc[i], ah, bh, acc[i]);
            wmma::mma_sync(acc[i], al, bh, acc[i]);
            wmma::mma_sync(acc[i], ah, bl, acc[i]);
        }
    }
    #pragma unroll
    for (int i = 0; i < 2; i++)
        wmma::store_matrix_sync(Csm + (mb + i) * 16 * LDF + n0, acc[i], LDF, wmma::mem_row_major);
}

// ===================== Fused kernel: hash encode + MLP + heads =====================
__global__ __launch_bounds__(BLOCK, 2) void fused_kernel(
    const float* __restrict__ pos, const float* __restrict__ dir,
    const float2* __restrict__ tab,
    const float* __restrict__ b0, const float* __restrict__ b1,
    const float* __restrict__ b2, const float* __restrict__ br,
    const float* __restrict__ wc, const float* __restrict__ bc,
    const float* __restrict__ wd, const float* __restrict__ bd,
    float* __restrict__ out)
{
    extern __shared__ char smraw[];
    float*         bufF  = (float*)(smraw + OFF_BUFF);
    __nv_bfloat16* actH  = (__nv_bfloat16*)(smraw + OFF_ACTH);
    __nv_bfloat16* actL  = (__nv_bfloat16*)(smraw + OFF_ACTL);
    __nv_bfloat16* dvH   = (__nv_bfloat16*)(smraw + OFF_DVH);
    __nv_bfloat16* dvL   = (__nv_bfloat16*)(smraw + OFF_DVL);
    float*         brep0 = (float*)(smraw + OFF_BREP0);
    float*         brep1 = (float*)(smraw + OFF_BREP1);
    float*         brep2 = (float*)(smraw + OFF_BREP2);
    float*         brepr = (float*)(smraw + OFF_BREPR);

    const int t  = threadIdx.x;
    const int w  = t >> 5;
    const int ib = blockIdx.x * PPB;

    // ================= Phase 1: hash encode (8 levels per thread) =============
    {
        const int pt = t & (PPB - 1);
        const int hf = t >> 7;
        const int i  = ib + pt;
        const float px = pos[3 * i], py = pos[3 * i + 1], pz = pos[3 * i + 2];

        #pragma unroll
        for (int j = 0; j < 8; j++) {
            const int l = 2 * j + hf;
            const float sc = c_scale[l];
            const float sx = px * sc, sy = py * sc, sz = pz * sc;
            const float fx = floorf(sx), fy = floorf(sy), fz = floorf(sz);
            const float ox = sx - fx, oy = sy - fy, oz = sz - fz;
            const unsigned hx0 = (unsigned)(int)fx;                 // x prime = 1
            const unsigned hx1 = (unsigned)(int)ceilf(sx);
            const unsigned hy0 = (unsigned)(int)fy * 2654435761u;
            const unsigned hy1 = (unsigned)(int)ceilf(sy) * 2654435761u;
            const unsigned hz0 = (unsigned)(int)fz * 805459861u;
            const unsigned hz1 = (unsigned)(int)ceilf(sz) * 805459861u;
            const unsigned lvl = ((unsigned)l) << TBITS;
            const float wx0 = 1.f - ox, wy0 = 1.f - oy, wz0 = 1.f - oz;

            float2 a = make_float2(0.f, 0.f);
            #pragma unroll
            for (int p = 0; p < 4; p++) {
                const unsigned hyz = ((p & 1) ? hy1 : hy0) ^ ((p & 2) ? hz1 : hz0);
                const unsigned i0 = (hx0 ^ hyz) & TMASK;
                const unsigned i1 = (hx1 ^ hyz) & TMASK;
                const float4 q = __ldg((const float4*)(tab + ((i0 & ~1u) + lvl)));
                const float2 lo = make_float2(q.x, q.y);
                const float2 hi = make_float2(q.z, q.w);
                float2 e0 = (i0 & 1u) ? hi : lo;
                float2 e1;
                if (i1 == (i0 ^ 1u)) {
                    e1 = (i0 & 1u) ? lo : hi;
                } else {
                    e1 = __ldg(&tab[i1 + lvl]);
                }
                const float wyz = ((p & 1) ? oy : wy0) * ((p & 2) ? oz : wz0);
                const float w0f = wx0 * wyz, w1f = ox * wyz;
                a = ffma2(make_float2(w0f, w0f), e0, a);
                a = ffma2(make_float2(w1f, w1f), e1, a);
            }
            __nv_bfloat16 h0, l0, h1, l1;
            split1(a.x, h0, l0);
            split1(a.y, h1, l1);
            __nv_bfloat162 hh; hh.x = h0; hh.y = h1;
            __nv_bfloat162 ll; ll.x = l0; ll.y = l1;
            *(__nv_bfloat162*)(actH + pt * LDAB + 2 * l) = hh;
            *(__nv_bfloat162*)(actL + pt * LDAB + 2 * l) = ll;
        }

        // ---- Direction encode -> dvH/dvL[pt][0..31] ----
        __nv_bfloat16* rh = dvH + pt * LDDV;
        __nv_bfloat16* rl = dvL + pt * LDDV;
        const float fr[4] = {1.f, 2.5198421f, 6.3496042f, 16.f};
        if (hf == 0) {
            const float dx = dir[3 * i], dy = dir[3 * i + 1];
            const float tx = 6.2831855f * dx, ty = 6.2831855f * dy;
            #pragma unroll
            for (int k = 0; k < 4; k++) {
                float s, c;
                sincosf(tx * fr[k], &s, &c);
                split1(s, rh[k],      rl[k]);
                split1(c, rh[12 + k], rl[12 + k]);
                sincosf(ty * fr[k], &s, &c);
                split1(s, rh[4 + k],  rl[4 + k]);
                split1(c, rh[16 + k], rl[16 + k]);
            }
        } else {
            const float dx = dir[3 * i], dy = dir[3 * i + 1], dz = dir[3 * i + 2];
            const float tz = 6.2831855f * dz;
            #pragma unroll
            for (int k = 0; k < 4; k++) {
                float s, c;
                sincosf(tz * fr[k], &s, &c);
                split1(s, rh[8 + k],  rl[8 + k]);
                split1(c, rh[20 + k], rl[20 + k]);
            }
            split1(dx, rh[24], rl[24]);
            split1(dy, rh[25], rl[25]);
            split1(dz, rh[26], rl[26]);
            #pragma unroll
            for (int k = 27; k < 32; k++) {
                rh[k] = __float2bfloat16_rn(0.f);
                rl[k] = __float2bfloat16_rn(0.f);
            }
        }
    }
    // ---- All bias replicas, filled once ----
    for (int k = t; k < 16 * 64; k += BLOCK) {
        const int row = k >> 6, col = k & 63;
        brep0[row * LDF + col] = __ldg(&b0[col]);
        brep1[row * LDF + col] = __ldg(&b1[col]);
        brep2[row * LDF + col] = __ldg(&b2[col]);
    }
    for (int k = t; k < 16 * 32; k += BLOCK)
        brepr[(k >> 5) * LDF + (k & 31)] = __ldg(&br[k & 31]);
    __syncthreads();

    // ---- Layer 0: [128x32] @ w0 + b0, relu -> bufF ----
    bf16_layer64<32, true>(actH, actL, g_w0h, g_w0l, bufF, brep0, w);
    __syncthreads();
    for (int k = t; k < 16 * PPB; k += BLOCK) {
        const int p = k & 127, fg = k >> 7;
        float4 v = *(float4*)(bufF + p * LDF + 4 * fg);
        split4_store(v, actH + p * LDAB + 4 * fg, actL + p * LDAB + 4 * fg);
    }
    __syncthreads();

    // ---- Layer 1: [128x64] @ w1 + b1, relu -> bufF ----
    bf16_layer64<64, true>(actH, actL, g_w1h, g_w1l, bufF, brep1, w);
    __syncthreads();
    for (int k = t; k < 16 * PPB; k += BLOCK) {
        const int p = k & 127, fg = k >> 7;
        float4 v = *(float4*)(bufF + p * LDF + 4 * fg);
        split4_store(v, actH + p * LDAB + 4 * fg, actL + p * LDAB + 4 * fg);
    }
    __syncthreads();

    // ---- Layer 2: [128x64] @ w2 + b2, linear -> bufF (= bp fp32) ----
    bf16_layer64<64, false>(actH, actL, g_w2h, g_w2l, bufF, brep2, w);
    __syncthreads();
    // bp fp32 -> actH/L (for head MMA); density tail reads bp fp32 now.
    for (int k = t; k < 16 * PPB; k += BLOCK) {
        const int p = k & 127, fg = k >> 7;
        float4 v = *(float4*)(bufF + p * LDF + 4 * fg);
        split4_store(v, actH + p * LDAB + 4 * fg, actL + p * LDAB + 4 * fg);
    }
    if (t < PPB) {
        // density = softplus(bp @ wd + bd)
        const float* r = bufF + t * LDF;
        float a = __ldg(&bd[0]);
        #pragma unroll
        for (int q = 0; q < 16; q++) {
            const float4 v = *(const float4*)(r + 4 * q);
            a = fmaf(v.x, __ldg(&wd[4 * q + 0]), a);
            a = fmaf(v.y, __ldg(&wd[4 * q + 1]), a);
            a = fmaf(v.z, __ldg(&wd[4 * q + 2]), a);
            a = fmaf(v.w, __ldg(&wd[4 * q + 3]), a);
        }
        out[4 * (ib + t) + 3] = fmaxf(a, 0.f) + log1pf(expf(-fabsf(a)));
    }
    __syncthreads();

    // ---- RGB head MMA: rgbh -> bufF[pt][0..31] ----
    bf16_head(actH, actL, dvH, dvL, bufF, brepr, w);
    __syncthreads();

    // ---- rgb tail ----
    if (t < PPB) {
        const int ii = ib + t;
        const float* r = bufF + t * LDF;
        float a0 = __ldg(&bc[0]), a1 = __ldg(&bc[1]), a2 = __ldg(&bc[2]);
        #pragma unroll
        for (int q = 0; q < 8; q++) {
            const float4 v = *(const float4*)(r + 4 * q);
            #pragma unroll
            for (int j = 0; j < 4; j++) {
                const float x = (&v.x)[j];
                const int kk = 4 * q + j;
                a0 = fmaf(x, __ldg(&wc[kk * 3 + 0]), a0);
                a1 = fmaf(x, __ldg(&wc[kk * 3 + 1]), a1);
                a2 = fmaf(x, __ldg(&wc[kk * 3 + 2]), a2);
            }
        }
        out[4 * ii + 0] = 1.f / (1.f + expf(-a0));
        out[4 * ii + 1] = 1.f / (1.f + expf(-a1));
        out[4 * ii + 2] = 1.f / (1.f + expf(-a2));
    }
}

extern "C" void kernel_launch(void* const* d_in, const int* in_sizes, int n_in,
                              void* d_out, int out_size) {
    (void)in_sizes; (void)n_in; (void)out_size;
    const float*  pos = (const float*)d_in[0];
    const float*  dir = (const float*)d_in[1];
    const float2* tab = (const float2*)d_in[2];
    const float *w0 = (const float*)d_in[3],  *b0 = (const float*)d_in[4];
    const float *w1 = (const float*)d_in[5],  *b1 = (const float*)d_in[6];
    const float *w2 = (const float*)d_in[7],  *b2 = (const float*)d_in[8];
    const float *wr = (const float*)d_in[9],  *br = (const float*)d_in[10];
    const float *wc = (const float*)d_in[11], *bc = (const float*)d_in[12];
    const float *wd = (const float*)d_in[13], *bd = (const float*)d_in[14];
    float* out = (float*)d_out;

    split_kernel<<<8, 256>>>(w0, w1, w2, wr);

    cudaFuncSetAttribute(fused_kernel,
                         cudaFuncAttributeMaxDynamicSharedMemorySize, SMEM_BYTES);
    fused_kernel<<<N_PTS / PPB, BLOCK, SMEM_BYTES>>>(
        pos, dir, tab, b0, b1, b2, br, wc, bc, wd, bd, out);
}

// round 16
// speedup vs baseline: 1.0993x; 1.0993x over previous
#include <cuda_runtime.h>
#include <cuda_bf16.h>
#include <mma.h>

using namespace nvcuda;

#define N_PTS   524288            // = 1 << 19
#define TBITS   19
#define TMASK   ((1u << TBITS) - 1u)
#define BLOCK   256
#define PPB     128
#define LDF     68                // fp32 buf stride (floats)
#define LDAB    72                // bf16 act stride (elems)
#define LDDV    40                // bf16 dvec stride (elems)
// smem byte offsets
#define OFF_BUFF  0               // [128][68] fp32 = 34816
#define OFF_ACTH  34816           // [128][72] bf16 = 18432
#define OFF_ACTL  53248
#define OFF_DVH   71680           // [128][40] bf16 = 10240
#define OFF_DVL   81920
#define OFF_BREP0 92160           // [16][68] fp32 = 4352 each
#define OFF_BREP1 96512
#define OFF_BREP2 100864
#define OFF_BREPR 105216
#define SMEM_BYTES 109568

// Pre-split bf16 weights (hi/lo), B-matrix layout [K][N] row-major
__device__ __align__(16) __nv_bfloat16 g_w0h[32 * 64], g_w0l[32 * 64];
__device__ __align__(16) __nv_bfloat16 g_w1h[64 * 64], g_w1l[64 * 64];
__device__ __align__(16) __nv_bfloat16 g_w2h[64 * 64], g_w2l[64 * 64];
__device__ __align__(16) __nv_bfloat16 g_wrh[91 * 32], g_wrl[91 * 32];

__device__ __forceinline__ float2 ffma2(float2 a, float2 b, float2 c) {
    float2 d;
    asm("fma.rn.f32x2 %0, %1, %2, %3;"
        : "=l"(reinterpret_cast<unsigned long long&>(d))
        : "l"(reinterpret_cast<unsigned long long&>(a)),
          "l"(reinterpret_cast<unsigned long long&>(b)),
          "l"(reinterpret_cast<unsigned long long&>(c)));
    return d;
}

__constant__ float c_scale[16] = {
    16.f, 21.f, 27.f, 36.f, 48.f, 64.f, 84.f, 111.f,
    147.f, 194.f, 256.f, 337.f, 445.f, 588.f, 776.f, 1024.f
};

__device__ __forceinline__ void split1(float x, __nv_bfloat16& h, __nv_bfloat16& l) {
    h = __float2bfloat16_rn(x);
    l = __float2bfloat16_rn(x - __bfloat162float(h));
}

__device__ __forceinline__ void split4_store(float4 v, __nv_bfloat16* ph, __nv_bfloat16* pl) {
    __nv_bfloat16 h[4], l[4];
    split1(v.x, h[0], l[0]); split1(v.y, h[1], l[1]);
    split1(v.z, h[2], l[2]); split1(v.w, h[3], l[3]);
    *(uint2*)ph = *(uint2*)h;
    *(uint2*)pl = *(uint2*)l;
}

// ===================== Kernel 0: pre-split weights to bf16 hi/lo =====================
__global__ __launch_bounds__(256) void split_kernel(
    const float* __restrict__ w0, const float* __restrict__ w1,
    const float* __restrict__ w2, const float* __restrict__ wr)
{
    const int t = blockIdx.x * 256 + threadIdx.x;
    for (int k = t; k < 32 * 64; k += gridDim.x * 256) split1(w0[k], g_w0h[k], g_w0l[k]);
    for (int k = t; k < 64 * 64; k += gridDim.x * 256) {
        split1(w1[k], g_w1h[k], g_w1l[k]);
        split1(w2[k], g_w2h[k], g_w2l[k]);
    }
    for (int k = t; k < 91 * 32; k += gridDim.x * 256) split1(wr[k], g_wrh[k], g_wrl[k]);
}

// [128xK] @ [Kx64] layer; 8 warps = 4 n-slices x 2 m-halves (4 m-tiles each).
// (Round-12 validated tiling: short fragment live ranges.)
template <int NK, bool RELU>
__device__ __forceinline__ void bf16_layer64(
    const __nv_bfloat16* Ah, const __nv_bfloat16* Al,
    const __nv_bfloat16* __restrict__ Bh, const __nv_bfloat16* __restrict__ Bl,
    float* Csm, const float* brep, int w)
{
    const int n0 = (w & 3) * 16;
    const int mb = (w >> 2) * 4;
    wmma::fragment<wmma::accumulator, 16, 16, 16, float> acc[4];
    #pragma unroll
    for (int i = 0; i < 4; i++)
        wmma::load_matrix_sync(acc[i], brep + n0, LDF, wmma::mem_row_major);

    #pragma unroll
    for (int k = 0; k < NK; k += 16) {
        wmma::fragment<wmma::matrix_b, 16, 16, 16, __nv_bfloat16, wmma::row_major> bh, bl;
        wmma::load_matrix_sync(bh, Bh + k * 64 + n0, 64);
        wmma::load_matrix_sync(bl, Bl + k * 64 + n0, 64);
        #pragma unroll
        for (int i = 0; i < 4; i++) {
            wmma::fragment<wmma::matrix_a, 16, 16, 16, __nv_bfloat16, wmma::row_major> ah, al;
            wmma::load_matrix_sync(ah, Ah + (mb + i) * 16 * LDAB + k, LDAB);
            wmma::load_matrix_sync(al, Al + (mb + i) * 16 * LDAB + k, LDAB);
            wmma::mma_sync(acc[i], ah, bh, acc[i]);
            wmma::mma_sync(acc[i], al, bh, acc[i]);
            wmma::mma_sync(acc[i], ah, bl, acc[i]);
        }
    }
    #pragma unroll
    for (int i = 0; i < 4; i++) {
        if (RELU) {
            #pragma unroll
            for (int e = 0; e < acc[i].num_elements; e++)
                acc[i].x[e] = fmaxf(acc[i].x[e], 0.f);
        }
        wmma::store_matrix_sync(Csm + (mb + i) * 16 * LDF + n0, acc[i], LDF, wmma::mem_row_major);
    }
}

// RGB head: rgbh[128][32] = dv[128][32] @ wr[0:32] + bp[128][64] @ wr[27:91]
__device__ __forceinline__ void bf16_head(
    const __nv_bfloat16* bpH, const __nv_bfloat16* bpL,
    const __nv_bfloat16* dvH, const __nv_bfloat16* dvL,
    float* Csm, const float* brep, int w)
{
    const int n0 = (w & 1) * 16;
    const int mb = (w >> 1) * 2;
    wmma::fragment<wmma::accumulator, 16, 16, 16, float> acc[2];
    #pragma unroll
    for (int i = 0; i < 2; i++)
        wmma::load_matrix_sync(acc[i], brep + n0, LDF, wmma::mem_row_major);

    #pragma unroll
    for (int k = 0; k < 64; k += 16) {     // base part: wr rows 27..90
        wmma::fragment<wmma::matrix_b, 16, 16, 16, __nv_bfloat16, wmma::row_major> bh, bl;
        wmma::load_matrix_sync(bh, g_wrh + (27 + k) * 32 + n0, 32);
        wmma::load_matrix_sync(bl, g_wrl + (27 + k) * 32 + n0, 32);
        #pragma unroll
        for (int i = 0; i < 2; i++) {
            wmma::fragment<wmma::matrix_a, 16, 16, 16, __nv_bfloat16, wmma::row_major> ah, al;
            wmma::load_matrix_sync(ah, bpH + (mb + i) * 16 * LDAB + k, LDAB);
            wmma::load_matrix_sync(al, bpL + (mb + i) * 16 * LDAB + k, LDAB);
            wmma::mma_sync(acc[i], ah, bh, acc[i]);
            wmma::mma_sync(acc[i], al, bh, acc[i]);
            wmma::mma_sync(acc[i], ah, bl, acc[i]);
        }
    }
    #pragma unroll
    for (int k = 0; k < 32; k += 16) {     // dir part: wr rows 0..31 (dv cols 27..31 = 0)
        wmma::fragment<wmma::matrix_b, 16, 16, 16, __nv_bfloat16, wmma::row_major> bh, bl;
        wmma::load_matrix_sync(bh, g_wrh + k * 32 + n0, 32);
        wmma::load_matrix_sync(bl, g_wrl + k * 32 + n0, 32);
        #pragma unroll
        for (int i = 0; i < 2; i++) {
            wmma::fragment<wmma::matrix_a, 16, 16, 16, __nv_bfloat16, wmma::row_major> ah, al;
            wmma::load_matrix_sync(ah, dvH + (mb + i) * 16 * LDDV + k, LDDV);
            wmma::load_matrix_sync(al, dvL + (mb + i) * 16 * LDDV + k, LDDV);
            wmma::mma_sync(acc[i], ah, bh, acc[i]);
            wmma::mma_sync(acc[i], al, bh, acc[i]);
            wmma::mma_sync(acc[i], ah, bl, acc[i]);
        }
    }
    #pragma unroll
    for (int i = 0; i < 2; i++)
        wmma::store_matrix_sync(Csm + (mb + i) * 16 * LDF + n0, acc[i], LDF, wmma::mem_row_major);
}

// ===================== Fused kernel: hash encode + MLP + heads =====================
__global__ __launch_bounds__(BLOCK, 2) void fused_kernel(
    const float* __restrict__ pos, const float* __restrict__ dir,
    const float2* __restrict__ tab,
    const float* __restrict__ b0, const float* __restrict__ b1,
    const float* __restrict__ b2, const float* __restrict__ br,
    const float* __restrict__ wc, const float* __restrict__ bc,
    const float* __restrict__ wd, const float* __restrict__ bd,
    float* __restrict__ out)
{
    extern __shared__ char smraw[];
    float*         bufF  = (float*)(smraw + OFF_BUFF);
    __nv_bfloat16* actH  = (__nv_bfloat16*)(smraw + OFF_ACTH);
    __nv_bfloat16* actL  = (__nv_bfloat16*)(smraw + OFF_ACTL);
    __nv_bfloat16* dvH   = (__nv_bfloat16*)(smraw + OFF_DVH);
    __nv_bfloat16* dvL   = (__nv_bfloat16*)(smraw + OFF_DVL);
    float*         brep0 = (float*)(smraw + OFF_BREP0);
    float*         brep1 = (float*)(smraw + OFF_BREP1);
    float*         brep2 = (float*)(smraw + OFF_BREP2);
    float*         brepr = (float*)(smraw + OFF_BREPR);

    const int t  = threadIdx.x;
    const int w  = t >> 5;
    const int ib = blockIdx.x * PPB;

    // ================= Phase 1: hash encode (8 levels per thread) =============
    {
        const int pt = t & (PPB - 1);
        const int hf = t >> 7;
        const int i  = ib + pt;
        const float px = pos[3 * i], py = pos[3 * i + 1], pz = pos[3 * i + 2];

        #pragma unroll
        for (int j = 0; j < 8; j++) {
            const int l = 2 * j + hf;
            const float sc = c_scale[l];
            const float sx = px * sc, sy = py * sc, sz = pz * sc;
            const float fx = floorf(sx), fy = floorf(sy), fz = floorf(sz);
            const float ox = sx - fx, oy = sy - fy, oz = sz - fz;
            const unsigned hx0 = (unsigned)(int)fx;                 // x prime = 1
            const unsigned hx1 = (unsigned)(int)ceilf(sx);
            const unsigned hy0 = (unsigned)(int)fy * 2654435761u;
            const unsigned hy1 = (unsigned)(int)ceilf(sy) * 2654435761u;
            const unsigned hz0 = (unsigned)(int)fz * 805459861u;
            const unsigned hz1 = (unsigned)(int)ceilf(sz) * 805459861u;
            const unsigned lvl = ((unsigned)l) << TBITS;
            const float wx0 = 1.f - ox, wy0 = 1.f - oy, wz0 = 1.f - oz;

            float2 a = make_float2(0.f, 0.f);
            #pragma unroll
            for (int p = 0; p < 4; p++) {
                const unsigned hyz = ((p & 1) ? hy1 : hy0) ^ ((p & 2) ? hz1 : hz0);
                const unsigned i0 = (hx0 ^ hyz) & TMASK;
                const unsigned i1 = (hx1 ^ hyz) & TMASK;
                const float4 q = __ldg((const float4*)(tab + ((i0 & ~1u) + lvl)));
                const float2 lo = make_float2(q.x, q.y);
                const float2 hi = make_float2(q.z, q.w);
                float2 e0 = (i0 & 1u) ? hi : lo;
                float2 e1;
                if (i1 == (i0 ^ 1u)) {
                    e1 = (i0 & 1u) ? lo : hi;
                } else {
                    e1 = __ldg(&tab[i1 + lvl]);
                }
                const float wyz = ((p & 1) ? oy : wy0) * ((p & 2) ? oz : wz0);
                const float w0f = wx0 * wyz, w1f = ox * wyz;
                a = ffma2(make_float2(w0f, w0f), e0, a);
                a = ffma2(make_float2(w1f, w1f), e1, a);
            }
            __nv_bfloat16 h0, l0, h1, l1;
            split1(a.x, h0, l0);
            split1(a.y, h1, l1);
            __nv_bfloat162 hh; hh.x = h0; hh.y = h1;
            __nv_bfloat162 ll; ll.x = l0; ll.y = l1;
            *(__nv_bfloat162*)(actH + pt * LDAB + 2 * l) = hh;
            *(__nv_bfloat162*)(actL + pt * LDAB + 2 * l) = ll;
        }

        // ---- Direction encode -> dvH/dvL[pt][0..31] ----
        __nv_bfloat16* rh = dvH + pt * LDDV;
        __nv_bfloat16* rl = dvL + pt * LDDV;
        const float fr[4] = {1.f, 2.5198421f, 6.3496042f, 16.f};
        if (hf == 0) {
            const float dx = dir[3 * i], dy = dir[3 * i + 1];
            const float tx = 6.2831855f * dx, ty = 6.2831855f * dy;
            #pragma unroll
            for (int k = 0; k < 4; k++) {
                float s, c;
                sincosf(tx * fr[k], &s, &c);
                split1(s, rh[k],      rl[k]);
                split1(c, rh[12 + k], rl[12 + k]);
                sincosf(ty * fr[k], &s, &c);
                split1(s, rh[4 + k],  rl[4 + k]);
                split1(c, rh[16 + k], rl[16 + k]);
            }
        } else {
            const float dx = dir[3 * i], dy = dir[3 * i + 1], dz = dir[3 * i + 2];
            const float tz = 6.2831855f * dz;
            #pragma unroll
            for (int k = 0; k < 4; k++) {
                float s, c;
                sincosf(tz * fr[k], &s, &c);
                split1(s, rh[8 + k],  rl[8 + k]);
                split1(c, rh[20 + k], rl[20 + k]);
            }
            split1(dx, rh[24], rl[24]);
            split1(dy, rh[25], rl[25]);
            split1(dz, rh[26], rl[26]);
            #pragma unroll
            for (int k = 27; k < 32; k++) {
                rh[k] = __float2bfloat16_rn(0.f);
                rl[k] = __float2bfloat16_rn(0.f);
            }
        }
    }
    // ---- All bias replicas, filled once ----
    for (int k = t; k < 16 * 64; k += BLOCK) {
        const int row = k >> 6, col = k & 63;
        const float v0 = __ldg(&b0[col]);
        const float v1 = __ldg(&b1[col]);
        const float v2 = __ldg(&b2[col]);
        brep0[row * LDF + col] = v0;
        brep1[row * LDF + col] = v1;
        brep2[row * LDF + col] = v2;
    }
    for (int k = t; k < 16 * 32; k += BLOCK)
        brepr[(k >> 5) * LDF + (k & 31)] = __ldg(&br[k & 31]);
    __syncthreads();

    // ---- Layer 0: [128x32] @ w0 + b0, relu -> bufF ----
    bf16_layer64<32, true>(actH, actL, g_w0h, g_w0l, bufF, brep0, w);
    __syncthreads();
    for (int k = t; k < 16 * PPB; k += BLOCK) {
        const int p = k & 127, fg = k >> 7;
        float4 v = *(float4*)(bufF + p * LDF + 4 * fg);
        split4_store(v, actH + p * LDAB + 4 * fg, actL + p * LDAB + 4 * fg);
    }
    __syncthreads();

    // ---- Layer 1: [128x64] @ w1 + b1, relu -> bufF ----
    bf16_layer64<64, true>(actH, actL, g_w1h, g_w1l, bufF, brep1, w);
    __syncthreads();
    for (int k = t; k < 16 * PPB; k += BLOCK) {
        const int p = k & 127, fg = k >> 7;
        float4 v = *(float4*)(bufF + p * LDF + 4 * fg);
        split4_store(v, actH + p * LDAB + 4 * fg, actL + p * LDAB + 4 * fg);
    }
    __syncthreads();

    // ---- Layer 2: [128x64] @ w2 + b2, linear -> bufF (= bp fp32) ----
    bf16_layer64<64, false>(actH, actL, g_w2h, g_w2l, bufF, brep2, w);
    __syncthreads();
    // bp fp32 -> actH/L (for head MMA); density tail reads bp fp32 now.
    for (int k = t; k < 16 * PPB; k += BLOCK) {
        const int p = k & 127, fg = k >> 7;
        float4 v = *(float4*)(bufF + p * LDF + 4 * fg);
        split4_store(v, actH + p * LDAB + 4 * fg, actL + p * LDAB + 4 * fg);
    }
    if (t < PPB) {
        // density = softplus(bp @ wd + bd)
        const float* r = bufF + t * LDF;
        float a = __ldg(&bd[0]);
        #pragma unroll
        for (int q = 0; q < 16; q++) {
            const float4 v = *(const float4*)(r + 4 * q);
            a = fmaf(v.x, __ldg(&wd[4 * q + 0]), a);
            a = fmaf(v.y, __ldg(&wd[4 * q + 1]), a);
            a = fmaf(v.z, __ldg(&wd[4 * q + 2]), a);
            a = fmaf(v.w, __ldg(&wd[4 * q + 3]), a);
        }
        out[4 * (ib + t) + 3] = fmaxf(a, 0.f) + log1pf(expf(-fabsf(a)));
    }
    __syncthreads();

    // ---- RGB head MMA: rgbh -> bufF[pt][0..31] ----
    bf16_head(actH, actL, dvH, dvL, bufF, brepr, w);
    __syncthreads();

    // ---- rgb tail ----
    if (t < PPB) {
        const int ii = ib + t;
        const float* r = bufF + t * LDF;
        float a0 = __ldg(&bc[0]), a1 = __ldg(&bc[1]), a2 = __ldg(&bc[2]);
        #pragma unroll
        for (int q = 0; q < 8; q++) {
            const float4 v = *(const float4*)(r + 4 * q);
            #pragma unroll
            for (int j = 0; j < 4; j++) {
                const float x = (&v.x)[j];
                const int kk = 4 * q + j;
                a0 = fmaf(x, __ldg(&wc[kk * 3 + 0]), a0);
                a1 = fmaf(x, __ldg(&wc[kk * 3 + 1]), a1);
                a2 = fmaf(x, __ldg(&wc[kk * 3 + 2]), a2);
            }
        }
        out[4 * ii + 0] = 1.f / (1.f + expf(-a0));
        out[4 * ii + 1] = 1.f / (1.f + expf(-a1));
        out[4 * ii + 2] = 1.f / (1.f + expf(-a2));
    }
}

extern "C" void kernel_launch(void* const* d_in, const int* in_sizes, int n_in,
                              void* d_out, int out_size) {
    (void)in_sizes; (void)n_in; (void)out_size;
    const float*  pos = (const float*)d_in[0];
    const float*  dir = (const float*)d_in[1];
    const float2* tab = (const float2*)d_in[2];
    const float *w0 = (const float*)d_in[3],  *b0 = (const float*)d_in[4];
    const float *w1 = (const float*)d_in[5],  *b1 = (const float*)d_in[6];
    const float *w2 = (const float*)d_in[7],  *b2 = (const float*)d_in[8];
    const float *wr = (const float*)d_in[9],  *br = (const float*)d_in[10];
    const float *wc = (const float*)d_in[11], *bc = (const float*)d_in[12];
    const float *wd = (const float*)d_in[13], *bd = (const float*)d_in[14];
    float* out = (float*)d_out;

    split_kernel<<<8, 256>>>(w0, w1, w2, wr);

    cudaFuncSetAttribute(fused_kernel,
                         cudaFuncAttributeMaxDynamicSharedMemorySize, SMEM_BYTES);
    fused_kernel<<<N_PTS / PPB, BLOCK, SMEM_BYTES>>>(
        pos, dir, tab, b0, b1, b2, br, wc, bc, wd, bd, out);
}

// round 17
// speedup vs baseline: 1.4310x; 1.3017x over previous
#include <cuda_runtime.h>
#include <cuda_bf16.h>
#include <mma.h>

using namespace nvcuda;

#define N_PTS   524288            // = 1 << 19
#define PT_BITS 19
#define TBITS   19
#define TMASK   ((1u << TBITS) - 1u)
#define BLOCK   256
#define PPB     128
#define LDF     68                // fp32 buf stride (floats)
#define LDAB    72                // bf16 act stride (elems)
#define LDDV    40                // bf16 dvec stride (elems)
// smem bytes: bufF + actH + actL + dvH + dvL + brep
#define OFF_BUFF 0
#define OFF_ACTH 34816
#define OFF_ACTL 53248
#define OFF_DVH  71680
#define OFF_DVL  81920
#define OFF_BREP 92160
#define SMEM_BYTES 96512

// Feature-major hash-encode scratch
__device__ float g_enc[32u * N_PTS];
// Pre-split bf16 weights (hi/lo), B-matrix layout [K][N] row-major
__device__ __align__(16) __nv_bfloat16 g_w0h[32 * 64], g_w0l[32 * 64];
__device__ __align__(16) __nv_bfloat16 g_w1h[64 * 64], g_w1l[64 * 64];
__device__ __align__(16) __nv_bfloat16 g_w2h[64 * 64], g_w2l[64 * 64];
__device__ __align__(16) __nv_bfloat16 g_wrh[91 * 32], g_wrl[91 * 32];

__device__ __forceinline__ float2 ffma2(float2 a, float2 b, float2 c) {
    float2 d;
    asm("fma.rn.f32x2 %0, %1, %2, %3;"
        : "=l"(reinterpret_cast<unsigned long long&>(d))
        : "l"(reinterpret_cast<unsigned long long&>(a)),
          "l"(reinterpret_cast<unsigned long long&>(b)),
          "l"(reinterpret_cast<unsigned long long&>(c)));
    return d;
}

__constant__ float c_scale[16] = {
    16.f, 21.f, 27.f, 36.f, 48.f, 64.f, 84.f, 111.f,
    147.f, 194.f, 256.f, 337.f, 445.f, 588.f, 776.f, 1024.f
};

__device__ __forceinline__ void split1(float x, __nv_bfloat16& h, __nv_bfloat16& l) {
    h = __float2bfloat16_rn(x);
    l = __float2bfloat16_rn(x - __bfloat162float(h));
}

__device__ __forceinline__ void split4_store(float4 v, __nv_bfloat16* ph, __nv_bfloat16* pl) {
    __nv_bfloat16 h[4], l[4];
    split1(v.x, h[0], l[0]); split1(v.y, h[1], l[1]);
    split1(v.z, h[2], l[2]); split1(v.w, h[3], l[3]);
    *(uint2*)ph = *(uint2*)h;
    *(uint2*)pl = *(uint2*)l;
}

// ===================== Kernel A: hash-grid encode (+ weight split in blocks 0..7) ==
__global__ __launch_bounds__(256) void encode_kernel(
    const float* __restrict__ pos, const float2* __restrict__ tab,
    const float* __restrict__ w0, const float* __restrict__ w1,
    const float* __restrict__ w2, const float* __restrict__ wr)
{
    // Blocks 0..7 additionally pre-split the MLP weights to bf16 hi/lo.
    if (blockIdx.x < 8) {
        const int ts = blockIdx.x * 256 + threadIdx.x;   // 0..2047
        for (int k = ts; k < 32 * 64; k += 2048) split1(w0[k], g_w0h[k], g_w0l[k]);
        for (int k = ts; k < 64 * 64; k += 2048) {
            split1(w1[k], g_w1h[k], g_w1l[k]);
            split1(w2[k], g_w2h[k], g_w2l[k]);
        }
        for (int k = ts; k < 91 * 32; k += 2048) split1(wr[k], g_wrh[k], g_wrl[k]);
    }

    const unsigned g  = blockIdx.x * 256u + threadIdx.x;
    const int      l  = (int)(g >> PT_BITS);
    const unsigned pt = g & (N_PTS - 1u);

    const float px = pos[3 * pt], py = pos[3 * pt + 1], pz = pos[3 * pt + 2];
    const float sc = c_scale[l];
    const float sx = px * sc, sy = py * sc, sz = pz * sc;
    const float fx = floorf(sx), fy = floorf(sy), fz = floorf(sz);
    const float ox = sx - fx, oy = sy - fy, oz = sz - fz;
    const unsigned hx0 = (unsigned)(int)fx;                 // x prime = 1
    const unsigned hx1 = (unsigned)(int)ceilf(sx);
    const unsigned hy0 = (unsigned)(int)fy * 2654435761u;
    const unsigned hy1 = (unsigned)(int)ceilf(sy) * 2654435761u;
    const unsigned hz0 = (unsigned)(int)fz * 805459861u;
    const unsigned hz1 = (unsigned)(int)ceilf(sz) * 805459861u;
    const unsigned lvl = ((unsigned)l) << TBITS;
    const float wx0 = 1.f - ox, wy0 = 1.f - oy, wz0 = 1.f - oz;

    float2 a = make_float2(0.f, 0.f);
    #pragma unroll
    for (int p = 0; p < 4; p++) {
        const unsigned hyz = ((p & 1) ? hy1 : hy0) ^ ((p & 2) ? hz1 : hz0);
        const unsigned i0 = (hx0 ^ hyz) & TMASK;
        const unsigned i1 = (hx1 ^ hyz) & TMASK;
        const float4 q = __ldg((const float4*)(tab + ((i0 & ~1u) + lvl)));
        const float2 lo = make_float2(q.x, q.y);
        const float2 hi = make_float2(q.z, q.w);
        float2 e0 = (i0 & 1u) ? hi : lo;
        float2 e1;
        if (i1 == (i0 ^ 1u)) {
            e1 = (i0 & 1u) ? lo : hi;
        } else {
            e1 = __ldg(&tab[i1 + lvl]);
        }
        const float wyz = ((p & 1) ? oy : wy0) * ((p & 2) ? oz : wz0);
        const float w0f = wx0 * wyz, w1f = ox * wyz;
        a = ffma2(make_float2(w0f, w0f), e0, a);
        a = ffma2(make_float2(w1f, w1f), e1, a);
    }
    g_enc[(2u * l)     * (unsigned)N_PTS + pt] = a.x;
    g_enc[(2u * l + 1) * (unsigned)N_PTS + pt] = a.y;
}

// [128xK] @ [Kx64] layer; 8 warps = 4 n-slices x 2 m-halves (4 m-tiles each).
template <int NK, bool RELU>
__device__ __forceinline__ void bf16_layer64(
    const __nv_bfloat16* Ah, const __nv_bfloat16* Al,
    const __nv_bfloat16* __restrict__ Bh, const __nv_bfloat16* __restrict__ Bl,
    float* Csm, const float* brep, int w)
{
    const int n0 = (w & 3) * 16;
    const int mb = (w >> 2) * 4;
    wmma::fragment<wmma::accumulator, 16, 16, 16, float> acc[4];
    #pragma unroll
    for (int i = 0; i < 4; i++)
        wmma::load_matrix_sync(acc[i], brep + n0, LDF, wmma::mem_row_major);

    #pragma unroll
    for (int k = 0; k < NK; k += 16) {
        wmma::fragment<wmma::matrix_b, 16, 16, 16, __nv_bfloat16, wmma::row_major> bh, bl;
        wmma::load_matrix_sync(bh, Bh + k * 64 + n0, 64);
        wmma::load_matrix_sync(bl, Bl + k * 64 + n0, 64);
        #pragma unroll
        for (int i = 0; i < 4; i++) {
            wmma::fragment<wmma::matrix_a, 16, 16, 16, __nv_bfloat16, wmma::row_major> ah, al;
            wmma::load_matrix_sync(ah, Ah + (mb + i) * 16 * LDAB + k, LDAB);
            wmma::load_matrix_sync(al, Al + (mb + i) * 16 * LDAB + k, LDAB);
            wmma::mma_sync(acc[i], ah, bh, acc[i]);
            wmma::mma_sync(acc[i], al, bh, acc[i]);
            wmma::mma_sync(acc[i], ah, bl, acc[i]);
        }
    }
    #pragma unroll
    for (int i = 0; i < 4; i++) {
        if (RELU) {
            #pragma unroll
            for (int e = 0; e < acc[i].num_elements; e++)
                acc[i].x[e] = fmaxf(acc[i].x[e], 0.f);
        }
        wmma::store_matrix_sync(Csm + (mb + i) * 16 * LDF + n0, acc[i], LDF, wmma::mem_row_major);
    }
}

// RGB head: rgbh[128][32] = dv[128][32] @ wr[0:32] + bp[128][64] @ wr[27:91]
__device__ __forceinline__ void bf16_head(
    const __nv_bfloat16* bpH, const __nv_bfloat16* bpL,
    const __nv_bfloat16* dvH, const __nv_bfloat16* dvL,
    float* Csm, const float* brep, int w)
{
    const int n0 = (w & 1) * 16;
    const int mb = (w >> 1) * 2;
    wmma::fragment<wmma::accumulator, 16, 16, 16, float> acc[2];
    #pragma unroll
    for (int i = 0; i < 2; i++)
        wmma::load_matrix_sync(acc[i], brep + n0, LDF, wmma::mem_row_major);

    #pragma unroll
    for (int k = 0; k < 64; k += 16) {     // base part: wr rows 27..90
        wmma::fragment<wmma::matrix_b, 16, 16, 16, __nv_bfloat16, wmma::row_major> bh, bl;
        wmma::load_matrix_sync(bh, g_wrh + (27 + k) * 32 + n0, 32);
        wmma::load_matrix_sync(bl, g_wrl + (27 + k) * 32 + n0, 32);
        #pragma unroll
        for (int i = 0; i < 2; i++) {
            wmma::fragment<wmma::matrix_a, 16, 16, 16, __nv_bfloat16, wmma::row_major> ah, al;
            wmma::load_matrix_sync(ah, bpH + (mb + i) * 16 * LDAB + k, LDAB);
            wmma::load_matrix_sync(al, bpL + (mb + i) * 16 * LDAB + k, LDAB);
            wmma::mma_sync(acc[i], ah, bh, acc[i]);
            wmma::mma_sync(acc[i], al, bh, acc[i]);
            wmma::mma_sync(acc[i], ah, bl, acc[i]);
        }
    }
    #pragma unroll
    for (int k = 0; k < 32; k += 16) {     // dir part: wr rows 0..31 (dv cols 27..31 = 0)
        wmma::fragment<wmma::matrix_b, 16, 16, 16, __nv_bfloat16, wmma::row_major> bh, bl;
        wmma::load_matrix_sync(bh, g_wrh + k * 32 + n0, 32);
        wmma::load_matrix_sync(bl, g_wrl + k * 32 + n0, 32);
        #pragma unroll
        for (int i = 0; i < 2; i++) {
            wmma::fragment<wmma::matrix_a, 16, 16, 16, __nv_bfloat16, wmma::row_major> ah, al;
            wmma::load_matrix_sync(ah, dvH + (mb + i) * 16 * LDDV + k, LDDV);
            wmma::load_matrix_sync(al, dvL + (mb + i) * 16 * LDDV + k, LDDV);
            wmma::mma_sync(acc[i], ah, bh, acc[i]);
            wmma::mma_sync(acc[i], al, bh, acc[i]);
            wmma::mma_sync(acc[i], ah, bl, acc[i]);
        }
    }
    #pragma unroll
    for (int i = 0; i < 2; i++)
        wmma::store_matrix_sync(Csm + (mb + i) * 16 * LDF + n0, acc[i], LDF, wmma::mem_row_major);
}

// ===================== Kernel B: MLP + heads (bf16-split wmma) =====================
__global__ __launch_bounds__(BLOCK, 2) void mlp_kernel(
    const float* __restrict__ dir,
    const float* __restrict__ b0, const float* __restrict__ b1,
    const float* __restrict__ b2, const float* __restrict__ br,
    const float* __restrict__ wc, const float* __restrict__ bc,
    const float* __restrict__ wd, const float* __restrict__ bd,
    float* __restrict__ out)
{
    extern __shared__ char smraw[];
    float*         bufF = (float*)(smraw + OFF_BUFF);          // [128][68] fp32
    __nv_bfloat16* actH = (__nv_bfloat16*)(smraw + OFF_ACTH);  // [128][72]
    __nv_bfloat16* actL = (__nv_bfloat16*)(smraw + OFF_ACTL);
    __nv_bfloat16* dvH  = (__nv_bfloat16*)(smraw + OFF_DVH);   // [128][40]
    __nv_bfloat16* dvL  = (__nv_bfloat16*)(smraw + OFF_DVL);
    float*         brep = (float*)(smraw + OFF_BREP);          // [16][68]

    const int t  = threadIdx.x;
    const int w  = t >> 5;
    const int ib = blockIdx.x * PPB;

    // ---- Stage enc: fp32 gather -> split -> bf16 hi/lo ----
    for (int k = t; k < 8 * PPB; k += BLOCK) {
        const int fg = k >> 7;
        const int p  = k & (PPB - 1);
        const unsigned gp = (unsigned)(ib + p);
        const int f = 4 * fg;
        float4 v;
        v.x = g_enc[(unsigned)(f    ) * N_PTS + gp];
        v.y = g_enc[(unsigned)(f + 1) * N_PTS + gp];
        v.z = g_enc[(unsigned)(f + 2) * N_PTS + gp];
        v.w = g_enc[(unsigned)(f + 3) * N_PTS + gp];
        split4_store(v, actH + p * LDAB + f, actL + p * LDAB + f);
    }

    // ---- Direction encode -> dvH/dvL[pt][0..31] (cols 27..31 zero) ----
    {
        const int pt = t & (PPB - 1);
        const int hf = t >> 7;
        const int i  = ib + pt;
        __nv_bfloat16* rh = dvH + pt * LDDV;
        __nv_bfloat16* rl = dvL + pt * LDDV;
        const float fr[4] = {1.f, 2.5198421f, 6.3496042f, 16.f};
        if (hf == 0) {
            const float dx = dir[3 * i], dy = dir[3 * i + 1];
            const float tx = 6.2831855f * dx, ty = 6.2831855f * dy;
            #pragma unroll
            for (int k = 0; k < 4; k++) {
                float s, c;
                sincosf(tx * fr[k], &s, &c);
                split1(s, rh[k],      rl[k]);
                split1(c, rh[12 + k], rl[12 + k]);
                sincosf(ty * fr[k], &s, &c);
                split1(s, rh[4 + k],  rl[4 + k]);
                split1(c, rh[16 + k], rl[16 + k]);
            }
        } else {
            const float dx = dir[3 * i], dy = dir[3 * i + 1], dz = dir[3 * i + 2];
            const float tz = 6.2831855f * dz;
            #pragma unroll
            for (int k = 0; k < 4; k++) {
                float s, c;
                sincosf(tz * fr[k], &s, &c);
                split1(s, rh[8 + k],  rl[8 + k]);
                split1(c, rh[20 + k], rl[20 + k]);
            }
            split1(dx, rh[24], rl[24]);
            split1(dy, rh[25], rl[25]);
            split1(dz, rh[26], rl[26]);
            #pragma unroll
            for (int k = 27; k < 32; k++) {
                rh[k] = __float2bfloat16_rn(0.f);
                rl[k] = __float2bfloat16_rn(0.f);
            }
        }
    }
    // ---- brep <- b0 ----
    for (int k = t; k < 16 * 64; k += BLOCK)
        brep[(k >> 6) * LDF + (k & 63)] = __ldg(&b0[k & 63]);
    __syncthreads();

    // ---- Layer 0: [128x32] @ w0 + b0, relu -> bufF ----
    bf16_layer64<32, true>(actH, actL, g_w0h, g_w0l, bufF, brep, w);
    __syncthreads();
    for (int k = t; k < 16 * PPB; k += BLOCK) {
        const int p = k & 127, fg = k >> 7;
        float4 v = *(float4*)(bufF + p * LDF + 4 * fg);
        split4_store(v, actH + p * LDAB + 4 * fg, actL + p * LDAB + 4 * fg);
    }
    for (int k = t; k < 16 * 64; k += BLOCK)
        brep[(k >> 6) * LDF + (k & 63)] = __ldg(&b1[k & 63]);
    __syncthreads();

    // ---- Layer 1: [128x64] @ w1 + b1, relu -> bufF ----
    bf16_layer64<64, true>(actH, actL, g_w1h, g_w1l, bufF, brep, w);
    __syncthreads();
    for (int k = t; k < 16 * PPB; k += BLOCK) {
        const int p = k & 127, fg = k >> 7;
        float4 v = *(float4*)(bufF + p * LDF + 4 * fg);
        split4_store(v, actH + p * LDAB + 4 * fg, actL + p * LDAB + 4 * fg);
    }
    for (int k = t; k < 16 * 64; k += BLOCK)
        brep[(k >> 6) * LDF + (k & 63)] = __ldg(&b2[k & 63]);
    __syncthreads();

    // ---- Layer 2: [128x64] @ w2 + b2, linear -> bufF (= bp fp32) ----
    bf16_layer64<64, false>(actH, actL, g_w2h, g_w2l, bufF, brep, w);
    __syncthreads();
    // bp fp32 -> actH/L (for head MMA); density tail reads bp fp32 now.
    for (int k = t; k < 16 * PPB; k += BLOCK) {
        const int p = k & 127, fg = k >> 7;
        float4 v = *(float4*)(bufF + p * LDF + 4 * fg);
        split4_store(v, actH + p * LDAB + 4 * fg, actL + p * LDAB + 4 * fg);
    }
    if (t < PPB) {
        // density = softplus(bp @ wd + bd)
        const float* r = bufF + t * LDF;
        float a = __ldg(&bd[0]);
        #pragma unroll
        for (int q = 0; q < 16; q++) {
            const float4 v = *(const float4*)(r + 4 * q);
            a = fmaf(v.x, __ldg(&wd[4 * q + 0]), a);
            a = fmaf(v.y, __ldg(&wd[4 * q + 1]), a);
            a = fmaf(v.z, __ldg(&wd[4 * q + 2]), a);
            a = fmaf(v.w, __ldg(&wd[4 * q + 3]), a);
        }
        out[4 * (ib + t) + 3] = fmaxf(a, 0.f) + log1pf(expf(-fabsf(a)));
    }
    // brep <- br (32 wide)
    for (int k = t; k < 16 * 32; k += BLOCK)
        brep[(k >> 5) * LDF + (k & 31)] = __ldg(&br[k & 31]);
    __syncthreads();

    // ---- RGB head MMA: rgbh -> bufF[pt][0..31] ----
    bf16_head(actH, actL, dvH, dvL, bufF, brep, w);
    __syncthreads();

    // ---- rgb tail ----
    if (t < PPB) {
        const int ii = ib + t;
        const float* r = bufF + t * LDF;
        float a0 = __ldg(&bc[0]), a1 = __ldg(&bc[1]), a2 = __ldg(&bc[2]);
        #pragma unroll
        for (int q = 0; q < 8; q++) {
            const float4 v = *(const float4*)(r + 4 * q);
            #pragma unroll
            for (int j = 0; j < 4; j++) {
                const float x = (&v.x)[j];
                const int kk = 4 * q + j;
                a0 = fmaf(x, __ldg(&wc[kk * 3 + 0]), a0);
                a1 = fmaf(x, __ldg(&wc[kk * 3 + 1]), a1);
                a2 = fmaf(x, __ldg(&wc[kk * 3 + 2]), a2);
            }
        }
        out[4 * ii + 0] = 1.f / (1.f + expf(-a0));
        out[4 * ii + 1] = 1.f / (1.f + expf(-a1));
        out[4 * ii + 2] = 1.f / (1.f + expf(-a2));
    }
}

extern "C" void kernel_launch(void* const* d_in, const int* in_sizes, int n_in,
                              void* d_out, int out_size) {
    (void)in_sizes; (void)n_in; (void)out_size;
    const float*  pos = (const float*)d_in[0];
    const float*  dir = (const float*)d_in[1];
    const float2* tab = (const float2*)d_in[2];
    const float *w0 = (const float*)d_in[3],  *b0 = (const float*)d_in[4];
    const float *w1 = (const float*)d_in[5],  *b1 = (const float*)d_in[6];
    const float *w2 = (const float*)d_in[7],  *b2 = (const float*)d_in[8];
    const float *wr = (const float*)d_in[9],  *br = (const float*)d_in[10];
    const float *wc = (const float*)d_in[11], *bc = (const float*)d_in[12];
    const float *wd = (const float*)d_in[13], *bd = (const float*)d_in[14];
    float* out = (float*)d_out;

    encode_kernel<<<(16 * N_PTS) / 256, 256>>>(pos, tab, w0, w1, w2, wr);

    cudaFuncSetAttribute(mlp_kernel,
                         cudaFuncAttributeMaxDynamicSharedMemorySize, SMEM_BYTES);
    mlp_kernel<<<N_PTS / PPB, BLOCK, SMEM_BYTES>>>(
        dir, b0, b1, b2, br, wc, bc, wd, bd, out);
}